// round 7
// baseline (speedup 1.0000x reference)
#include <cuda_runtime.h>
#include <cuda_fp16.h>
#include <math.h>

// GATv2 x3 + pooling: CSR + ILP4 online-softmax fused edge pass (fp16 xl gathers),
// dual (Wl+Wr) register-tiled linears, SMEM-staged pooling.
namespace {
constexpr int NN = 50000;
constexpr int NE = 800000;
constexpr int ET = NE + NN;
constexpr int NG = 16;
constexpr int TB = 256;
}

// ---------------- scratch ---------------------------------------------------
__device__ __align__(16) __half g_xlh[(size_t)NN * 128];   // fp16 source-transform
__device__ __align__(16) float  g_xr[(size_t)NN * 128];
__device__ __align__(16) float  g_h[(size_t)NN * 128];
__device__ int g_deg[NN];
__device__ int g_rowptr[NN + 1];
__device__ int g_cur[NN];
__device__ int g_csrc[ET];
__device__ float g_psum[NG * 32];
__device__ float g_pmax[NG * 32];
__device__ float g_cntf[NG];

__device__ __forceinline__ void atomicMaxF(float* a, float v) {
    if (v >= 0.f) atomicMax((int*)a, __float_as_int(v));
    else          atomicMin((unsigned int*)a, __float_as_uint(v));
}

__device__ __forceinline__ unsigned pack_h2(float a, float b) {
    __half2 h = __floats2half2_rn(a, b);
    return *reinterpret_cast<unsigned*>(&h);
}
__device__ __forceinline__ float4 unpack_f4(uint2 r) {
    __half2 v0 = *reinterpret_cast<__half2*>(&r.x);
    __half2 v1 = *reinterpret_cast<__half2*>(&r.y);
    float2 f0 = __half22float2(v0);
    float2 f1 = __half22float2(v1);
    return make_float4(f0.x, f0.y, f1.x, f1.y);
}

// ---------------- CSR build -------------------------------------------------
__global__ void deg_init_kernel() {
    int i = blockIdx.x * blockDim.x + threadIdx.x;
    if (i < NN) g_deg[i] = 1;            // self loop
}
__global__ void deg_count_kernel(const int* __restrict__ ei) {
    int e = blockIdx.x * blockDim.x + threadIdx.x;
    if (e < NE) atomicAdd(&g_deg[ei[NE + e]], 1);
}
__global__ void scan_kernel() {
    __shared__ int part[1024];
    const int tid = threadIdx.x;
    const int chunk = (NN + 1023) / 1024;
    const int beg = tid * chunk;
    const int end = min(beg + chunk, NN);
    int s = 0;
    for (int i = beg; i < end; i++) s += g_deg[i];
    part[tid] = s;
    __syncthreads();
    if (tid == 0) {
        int run = 0;
        for (int i = 0; i < 1024; i++) { int t = part[i]; part[i] = run; run += t; }
    }
    __syncthreads();
    int run = part[tid];
    for (int i = beg; i < end; i++) {
        g_rowptr[i] = run;
        g_cur[i] = run;
        run += g_deg[i];
    }
    if (tid == 0) g_rowptr[NN] = ET;
}
__global__ void fill_kernel(const int* __restrict__ ei) {
    int e = blockIdx.x * blockDim.x + threadIdx.x;
    if (e >= ET) return;
    int src, dst;
    if (e < NE) { src = ei[e]; dst = ei[NE + e]; }
    else        { src = e - NE; dst = src; }
    int pos = atomicAdd(&g_cur[dst], 1);
    g_csrc[pos] = src;
}

// ---------------- dual linear: Yl(fp16) = X@Wl+Bl, Yr(fp32) = X@Wr+Br -------
template<int IN, int OUT>
__global__ __launch_bounds__(256)
void linear_dual_kernel(const float* __restrict__ X,
                        const float* __restrict__ Wl, const float* __restrict__ Bl,
                        const float* __restrict__ Wr, const float* __restrict__ Br,
                        __half* __restrict__ Yl, float* __restrict__ Yr) {
    constexpr int TO  = OUT / 8;
    constexpr int NGR = 256 / TO;
    constexpr int NPB = NGR * 4;
    constexpr int KT  = (IN < 32) ? IN : 32;

    __shared__ float Xs[KT][NPB + 4];
    __shared__ float Wsl[KT][OUT];
    __shared__ float Wsr[KT][OUT];

    const int tid = threadIdx.x;
    const int og  = tid % TO;
    const int ng  = tid / TO;
    const int nb  = blockIdx.x * NPB;

    float accl[4][8], accr[4][8];
#pragma unroll
    for (int i = 0; i < 4; i++)
#pragma unroll
        for (int j = 0; j < 8; j++) { accl[i][j] = 0.f; accr[i][j] = 0.f; }

    for (int kt = 0; kt < IN; kt += KT) {
        __syncthreads();
        for (int idx = tid; idx < KT * OUT / 4; idx += 256) {
            const int k = idx / (OUT / 4), o4 = idx % (OUT / 4);
            ((float4*)Wsl[k])[o4] = ((const float4*)(Wl + (size_t)(kt + k) * OUT))[o4];
            ((float4*)Wsr[k])[o4] = ((const float4*)(Wr + (size_t)(kt + k) * OUT))[o4];
        }
        for (int idx = tid; idx < NPB * (KT / 4); idx += 256) {
            const int ni = idx / (KT / 4), f4 = idx % (KT / 4);
            const int gn = nb + ni;
            float4 xv = make_float4(0.f, 0.f, 0.f, 0.f);
            if (gn < NN)
                xv = ((const float4*)(X + (size_t)gn * IN + kt))[f4];
            Xs[f4 * 4 + 0][ni] = xv.x;
            Xs[f4 * 4 + 1][ni] = xv.y;
            Xs[f4 * 4 + 2][ni] = xv.z;
            Xs[f4 * 4 + 3][ni] = xv.w;
        }
        __syncthreads();
#pragma unroll
        for (int k = 0; k < KT; k++) {
            float xv[4];
#pragma unroll
            for (int i = 0; i < 4; i++) xv[i] = Xs[k][ng * 4 + i];
            const float4 wl0 = ((const float4*)&Wsl[k][og * 8])[0];
            const float4 wl1 = ((const float4*)&Wsl[k][og * 8])[1];
            const float4 wr0 = ((const float4*)&Wsr[k][og * 8])[0];
            const float4 wr1 = ((const float4*)&Wsr[k][og * 8])[1];
#pragma unroll
            for (int i = 0; i < 4; i++) {
                accl[i][0] += xv[i] * wl0.x; accl[i][1] += xv[i] * wl0.y;
                accl[i][2] += xv[i] * wl0.z; accl[i][3] += xv[i] * wl0.w;
                accl[i][4] += xv[i] * wl1.x; accl[i][5] += xv[i] * wl1.y;
                accl[i][6] += xv[i] * wl1.z; accl[i][7] += xv[i] * wl1.w;
                accr[i][0] += xv[i] * wr0.x; accr[i][1] += xv[i] * wr0.y;
                accr[i][2] += xv[i] * wr0.z; accr[i][3] += xv[i] * wr0.w;
                accr[i][4] += xv[i] * wr1.x; accr[i][5] += xv[i] * wr1.y;
                accr[i][6] += xv[i] * wr1.z; accr[i][7] += xv[i] * wr1.w;
            }
        }
    }

    const float4 bl0 = ((const float4*)(Bl + og * 8))[0];
    const float4 bl1 = ((const float4*)(Bl + og * 8))[1];
    const float4 br0 = ((const float4*)(Br + og * 8))[0];
    const float4 br1 = ((const float4*)(Br + og * 8))[1];
#pragma unroll
    for (int i = 0; i < 4; i++) {
        const int node = nb + ng * 4 + i;
        if (node >= NN) continue;
        uint4 hv;
        hv.x = pack_h2(accl[i][0] + bl0.x, accl[i][1] + bl0.y);
        hv.y = pack_h2(accl[i][2] + bl0.z, accl[i][3] + bl0.w);
        hv.z = pack_h2(accl[i][4] + bl1.x, accl[i][5] + bl1.y);
        hv.w = pack_h2(accl[i][6] + bl1.z, accl[i][7] + bl1.w);
        *(uint4*)(Yl + (size_t)node * OUT + og * 8) = hv;
        float4 o;
        o = make_float4(accr[i][0]+br0.x, accr[i][1]+br0.y, accr[i][2]+br0.z, accr[i][3]+br0.w);
        ((float4*)(Yr + (size_t)node * OUT + og * 8))[0] = o;
        o = make_float4(accr[i][4]+br1.x, accr[i][5]+br1.y, accr[i][6]+br1.z, accr[i][7]+br1.w);
        ((float4*)(Yr + (size_t)node * OUT + og * 8))[1] = o;
    }
}

// ---------------- fused GATv2 edge pass (CT=128, H=2), warp/dst, ILP4 -------
__global__ void gat_fused128_kernel(const float* __restrict__ att,
                                    const float* __restrict__ B,
                                    float* __restrict__ out) {
    const int node = (blockIdx.x * blockDim.x + threadIdx.x) >> 5;
    if (node >= NN) return;
    const int lane = threadIdx.x & 31;

    const float4 xrv  = *(const float4*)(g_xr + (size_t)node * 128 + lane * 4);
    const float4 attv = *(const float4*)(att + lane * 4);

    int p  = g_rowptr[node];
    const int pe = g_rowptr[node + 1];

    float  m[4] = {-INFINITY, -INFINITY, -INFINITY, -INFINITY};
    float  dd[4] = {0.f, 0.f, 0.f, 0.f};
    float4 A[4];
#pragma unroll
    for (int j = 0; j < 4; j++) A[j] = make_float4(0.f, 0.f, 0.f, 0.f);

    for (; p + 3 < pe; p += 4) {
        int s[4];
#pragma unroll
        for (int j = 0; j < 4; j++) s[j] = g_csrc[p + j];
        float4 a[4];
#pragma unroll
        for (int j = 0; j < 4; j++)
            a[j] = unpack_f4(*(const uint2*)(g_xlh + (size_t)s[j] * 128 + lane * 4));

        float pp[4];
#pragma unroll
        for (int j = 0; j < 4; j++) {
            float t, sc = 0.f;
            t = a[j].x + xrv.x; t = t > 0.f ? t : 0.2f * t; sc += t * attv.x;
            t = a[j].y + xrv.y; t = t > 0.f ? t : 0.2f * t; sc += t * attv.y;
            t = a[j].z + xrv.z; t = t > 0.f ? t : 0.2f * t; sc += t * attv.z;
            t = a[j].w + xrv.w; t = t > 0.f ? t : 0.2f * t; sc += t * attv.w;
            pp[j] = sc;
        }
#pragma unroll
        for (int off = 1; off <= 8; off <<= 1)
#pragma unroll
            for (int j = 0; j < 4; j++)
                pp[j] += __shfl_xor_sync(0xffffffffu, pp[j], off);
#pragma unroll
        for (int j = 0; j < 4; j++) {
            const float nm = fmaxf(m[j], pp[j]);
            const float sc = __expf(m[j] - nm);
            const float w  = __expf(pp[j] - nm);
            dd[j] = dd[j] * sc + w;
            A[j].x = A[j].x * sc + w * a[j].x;
            A[j].y = A[j].y * sc + w * a[j].y;
            A[j].z = A[j].z * sc + w * a[j].z;
            A[j].w = A[j].w * sc + w * a[j].w;
            m[j] = nm;
        }
    }
    for (; p < pe; ++p) {   // tail -> state 0
        const int s0 = g_csrc[p];
        const float4 a0 = unpack_f4(*(const uint2*)(g_xlh + (size_t)s0 * 128 + lane * 4));
        float t, p0 = 0.f;
        t = a0.x + xrv.x; t = t > 0.f ? t : 0.2f * t; p0 += t * attv.x;
        t = a0.y + xrv.y; t = t > 0.f ? t : 0.2f * t; p0 += t * attv.y;
        t = a0.z + xrv.z; t = t > 0.f ? t : 0.2f * t; p0 += t * attv.z;
        t = a0.w + xrv.w; t = t > 0.f ? t : 0.2f * t; p0 += t * attv.w;
#pragma unroll
        for (int off = 1; off <= 8; off <<= 1)
            p0 += __shfl_xor_sync(0xffffffffu, p0, off);
        const float nm = fmaxf(m[0], p0);
        const float sc = __expf(m[0] - nm);
        const float w  = __expf(p0 - nm);
        dd[0] = dd[0] * sc + w;
        A[0].x = A[0].x * sc + w * a0.x;
        A[0].y = A[0].y * sc + w * a0.y;
        A[0].z = A[0].z * sc + w * a0.z;
        A[0].w = A[0].w * sc + w * a0.w;
        m[0] = nm;
    }
    // merge 4 states (m[0] always finite: deg >= 1)
    float M = fmaxf(fmaxf(m[0], m[1]), fmaxf(m[2], m[3]));
    float d = 0.f;
    float4 acc = make_float4(0.f, 0.f, 0.f, 0.f);
#pragma unroll
    for (int j = 0; j < 4; j++) {
        const float sj = (m[j] == -INFINITY) ? 0.f : __expf(m[j] - M);
        d += dd[j] * sj;
        acc.x += A[j].x * sj; acc.y += A[j].y * sj;
        acc.z += A[j].z * sj; acc.w += A[j].w * sj;
    }

    const float inv = 1.f / (d + 1e-16f);
    const float4 bv = *(const float4*)(B + lane * 4);
    float4 o;
    o.x = acc.x * inv + bv.x; o.x = o.x > 0.f ? o.x : expm1f(o.x);
    o.y = acc.y * inv + bv.y; o.y = o.y > 0.f ? o.y : expm1f(o.y);
    o.z = acc.z * inv + bv.z; o.z = o.z > 0.f ? o.z : expm1f(o.z);
    o.w = acc.w * inv + bv.w; o.w = o.w > 0.f ? o.w : expm1f(o.w);
    *(float4*)(out + (size_t)node * 128 + lane * 4) = o;
}

// ---------------- fused GATv2 edge pass (CT=32, H=1), warp/dst, ILP4 --------
__global__ void gat_fused32_kernel(const float* __restrict__ att,
                                   const float* __restrict__ B,
                                   float* __restrict__ out) {
    const int node = (blockIdx.x * blockDim.x + threadIdx.x) >> 5;
    if (node >= NN) return;
    const int lane = threadIdx.x & 31;

    const float xrv  = g_xr[(size_t)node * 32 + lane];
    const float attv = att[lane];

    int p  = g_rowptr[node];
    const int pe = g_rowptr[node + 1];

    float m[4] = {-INFINITY, -INFINITY, -INFINITY, -INFINITY};
    float dd[4] = {0.f, 0.f, 0.f, 0.f};
    float A[4] = {0.f, 0.f, 0.f, 0.f};

    for (; p + 3 < pe; p += 4) {
        float a[4], pp[4];
#pragma unroll
        for (int j = 0; j < 4; j++) {
            const int s = g_csrc[p + j];
            a[j] = __half2float(g_xlh[(size_t)s * 32 + lane]);
            float t = a[j] + xrv; t = t > 0.f ? t : 0.2f * t;
            pp[j] = t * attv;
        }
#pragma unroll
        for (int off = 1; off <= 16; off <<= 1)
#pragma unroll
            for (int j = 0; j < 4; j++)
                pp[j] += __shfl_xor_sync(0xffffffffu, pp[j], off);
#pragma unroll
        for (int j = 0; j < 4; j++) {
            const float nm = fmaxf(m[j], pp[j]);
            const float sc = __expf(m[j] - nm);
            const float w  = __expf(pp[j] - nm);
            dd[j] = dd[j] * sc + w; A[j] = A[j] * sc + w * a[j]; m[j] = nm;
        }
    }
    for (; p < pe; ++p) {
        const int s = g_csrc[p];
        const float a0 = __half2float(g_xlh[(size_t)s * 32 + lane]);
        float t = a0 + xrv; t = t > 0.f ? t : 0.2f * t;
        float p0 = t * attv;
#pragma unroll
        for (int off = 1; off <= 16; off <<= 1)
            p0 += __shfl_xor_sync(0xffffffffu, p0, off);
        const float nm = fmaxf(m[0], p0);
        const float sc = __expf(m[0] - nm);
        const float w  = __expf(p0 - nm);
        dd[0] = dd[0] * sc + w; A[0] = A[0] * sc + w * a0; m[0] = nm;
    }
    float M = fmaxf(fmaxf(m[0], m[1]), fmaxf(m[2], m[3]));
    float d = 0.f, acc = 0.f;
#pragma unroll
    for (int j = 0; j < 4; j++) {
        const float sj = (m[j] == -INFINITY) ? 0.f : __expf(m[j] - M);
        d += dd[j] * sj; acc += A[j] * sj;
    }

    float o = acc / (d + 1e-16f) + B[lane];
    o = o > 0.f ? o : expm1f(o);
    out[(size_t)node * 32 + lane] = o;
}

// ---------------- pooling ----------------------------------------------------
__global__ void pool_init_kernel() {
    int i = blockIdx.x * blockDim.x + threadIdx.x;
    if (i < NG * 32) { g_psum[i] = 0.f; g_pmax[i] = -INFINITY; }
    if (i < NG) g_cntf[i] = 0.f;
}

__global__ __launch_bounds__(256)
void pool_accum_kernel(const float* __restrict__ h,
                       const int* __restrict__ batch) {
    __shared__ float ssum[NG * 32];
    __shared__ float smax[NG * 32];
    __shared__ int   scnt[NG];
    const int tid = threadIdx.x;
    for (int i = tid; i < NG * 32; i += 256) { ssum[i] = 0.f; smax[i] = -INFINITY; }
    if (tid < NG) scnt[tid] = 0;
    __syncthreads();

    const int warp = tid >> 5, lane = tid & 31;
    const int nbase = blockIdx.x * 256 + warp * 32;
#pragma unroll 4
    for (int i = 0; i < 32; i++) {
        const int node = nbase + i;
        if (node >= NN) break;
        const int g = batch[node];
        const float v = h[(size_t)node * 32 + lane];
        atomicAdd(&ssum[g * 32 + lane], v);
        atomicMaxF(&smax[g * 32 + lane], v);
        if (lane == 0) atomicAdd(&scnt[g], 1);
    }
    __syncthreads();

    for (int i = tid; i < NG * 32; i += 256) {
        if (ssum[i] != 0.f) atomicAdd(&g_psum[i], ssum[i]);
        if (smax[i] != -INFINITY) atomicMaxF(&g_pmax[i], smax[i]);
    }
    if (tid < NG && scnt[tid] > 0) atomicAdd(&g_cntf[tid], (float)scnt[tid]);
}

__global__ void pool_final_kernel(float* __restrict__ out) {
    const int i = blockIdx.x * blockDim.x + threadIdx.x;
    if (i >= NG * 64) return;
    const int g = i / 64, c = i % 64;
    out[i] = (c < 32) ? g_psum[g * 32 + c] / g_cntf[g]
                      : g_pmax[g * 32 + (c - 32)];
}

// ---------------- launch ------------------------------------------------------
static inline int gridFor(long long n) { return (int)((n + TB - 1) / TB); }

extern "C" void kernel_launch(void* const* d_in, const int* in_sizes, int n_in,
                              void* d_out, int out_size) {
    const float* x     = (const float*)d_in[0];
    const int*   ei    = (const int*)d_in[1];
    const int*   batch = (const int*)d_in[2];
    const float *Wl1=(const float*)d_in[3],  *bl1=(const float*)d_in[4];
    const float *Wr1=(const float*)d_in[5],  *br1=(const float*)d_in[6];
    const float *att1=(const float*)d_in[7], *b1=(const float*)d_in[8];
    const float *Wl2=(const float*)d_in[9],  *bl2=(const float*)d_in[10];
    const float *Wr2=(const float*)d_in[11], *br2=(const float*)d_in[12];
    const float *att2=(const float*)d_in[13],*b2=(const float*)d_in[14];
    const float *Wl3=(const float*)d_in[15], *bl3=(const float*)d_in[16];
    const float *Wr3=(const float*)d_in[17], *br3=(const float*)d_in[18];
    const float *att3=(const float*)d_in[19],*b3=(const float*)d_in[20];

    __half* p_xlh;
    float *p_xr, *p_h;
    cudaGetSymbolAddress((void**)&p_xlh, g_xlh);
    cudaGetSymbolAddress((void**)&p_xr,  g_xr);
    cudaGetSymbolAddress((void**)&p_h,   g_h);

    const int gNodeWarp = gridFor((long long)NN * 32);
    const int gLin128   = (NN + 63) / 64;
    const int gLin32    = (NN + 255) / 256;
    const int gPool     = (NN + 255) / 256;

    // ---- CSR (dst-indexed) build, reused by all 3 layers
    deg_init_kernel<<<gridFor(NN), TB>>>();
    deg_count_kernel<<<gridFor(NE), TB>>>(ei);
    scan_kernel<<<1, 1024>>>();
    fill_kernel<<<gridFor(ET), TB>>>(ei);

    // ---- layer 1: 8 -> 128 (H=2, C=64)
    linear_dual_kernel<8, 128><<<gLin128, 256>>>(x, Wl1, bl1, Wr1, br1, p_xlh, p_xr);
    gat_fused128_kernel<<<gNodeWarp, TB>>>(att1, b1, p_h);

    // ---- layer 2: 128 -> 128 (H=2, C=64)
    linear_dual_kernel<128, 128><<<gLin128, 256>>>(p_h, Wl2, bl2, Wr2, br2, p_xlh, p_xr);
    gat_fused128_kernel<<<gNodeWarp, TB>>>(att2, b2, p_h);

    // ---- layer 3: 128 -> 32 (H=1, C=32)
    linear_dual_kernel<128, 32><<<gLin32, 256>>>(p_h, Wl3, bl3, Wr3, br3, p_xlh, p_xr);
    gat_fused32_kernel<<<gNodeWarp, TB>>>(att3, b3, p_h);

    // ---- pooling
    pool_init_kernel<<<gridFor(NG * 32), TB>>>();
    pool_accum_kernel<<<gPool, 256>>>(p_h, batch);
    pool_final_kernel<<<gridFor(NG * 64), TB>>>((float*)d_out);
}

// round 8
// speedup vs baseline: 1.3230x; 1.3230x over previous
#include <cuda_runtime.h>
#include <math.h>

// GATv2 x3 + pooling: CSR + ILP4 online-softmax fused edge pass (fp32,
// software-pipelined gathers), dual (Wl+Wr) register-tiled linears,
// SMEM-staged pooling.
namespace {
constexpr int NN = 50000;
constexpr int NE = 800000;
constexpr int ET = NE + NN;
constexpr int NG = 16;
constexpr int TB = 256;
}

// ---------------- scratch ---------------------------------------------------
__device__ __align__(16) float g_xl[(size_t)NN * 128];
__device__ __align__(16) float g_xr[(size_t)NN * 128];
__device__ __align__(16) float g_h[(size_t)NN * 128];
__device__ int g_deg[NN];
__device__ int g_rowptr[NN + 1];
__device__ int g_cur[NN];
__device__ int g_csrc[ET];
__device__ float g_psum[NG * 32];
__device__ float g_pmax[NG * 32];
__device__ float g_cntf[NG];

__device__ __forceinline__ void atomicMaxF(float* a, float v) {
    if (v >= 0.f) atomicMax((int*)a, __float_as_int(v));
    else          atomicMin((unsigned int*)a, __float_as_uint(v));
}

// ---------------- CSR build -------------------------------------------------
__global__ void deg_init_kernel() {
    int i = blockIdx.x * blockDim.x + threadIdx.x;
    if (i < NN) g_deg[i] = 1;            // self loop
}
__global__ void deg_count_kernel(const int* __restrict__ ei) {
    int e = blockIdx.x * blockDim.x + threadIdx.x;
    if (e < NE) atomicAdd(&g_deg[ei[NE + e]], 1);
}
__global__ void scan_kernel() {
    __shared__ int part[1024];
    const int tid = threadIdx.x;
    const int chunk = (NN + 1023) / 1024;
    const int beg = tid * chunk;
    const int end = min(beg + chunk, NN);
    int s = 0;
    for (int i = beg; i < end; i++) s += g_deg[i];
    part[tid] = s;
    __syncthreads();
    if (tid == 0) {
        int run = 0;
        for (int i = 0; i < 1024; i++) { int t = part[i]; part[i] = run; run += t; }
    }
    __syncthreads();
    int run = part[tid];
    for (int i = beg; i < end; i++) {
        g_rowptr[i] = run;
        g_cur[i] = run;
        run += g_deg[i];
    }
    if (tid == 0) g_rowptr[NN] = ET;
}
__global__ void fill_kernel(const int* __restrict__ ei) {
    int e = blockIdx.x * blockDim.x + threadIdx.x;
    if (e >= ET) return;
    int src, dst;
    if (e < NE) { src = ei[e]; dst = ei[NE + e]; }
    else        { src = e - NE; dst = src; }
    int pos = atomicAdd(&g_cur[dst], 1);
    g_csrc[pos] = src;
}

// ---------------- dual linear: Yl = X@Wl+Bl, Yr = X@Wr+Br -------------------
template<int IN, int OUT>
__global__ __launch_bounds__(256)
void linear_dual_kernel(const float* __restrict__ X,
                        const float* __restrict__ Wl, const float* __restrict__ Bl,
                        const float* __restrict__ Wr, const float* __restrict__ Br,
                        float* __restrict__ Yl, float* __restrict__ Yr) {
    constexpr int TO  = OUT / 8;
    constexpr int NGR = 256 / TO;
    constexpr int NPB = NGR * 4;
    constexpr int KT  = (IN < 32) ? IN : 32;

    __shared__ float Xs[KT][NPB + 4];
    __shared__ float Wsl[KT][OUT];
    __shared__ float Wsr[KT][OUT];

    const int tid = threadIdx.x;
    const int og  = tid % TO;
    const int ng  = tid / TO;
    const int nb  = blockIdx.x * NPB;

    float accl[4][8], accr[4][8];
#pragma unroll
    for (int i = 0; i < 4; i++)
#pragma unroll
        for (int j = 0; j < 8; j++) { accl[i][j] = 0.f; accr[i][j] = 0.f; }

    for (int kt = 0; kt < IN; kt += KT) {
        __syncthreads();
        for (int idx = tid; idx < KT * OUT / 4; idx += 256) {
            const int k = idx / (OUT / 4), o4 = idx % (OUT / 4);
            ((float4*)Wsl[k])[o4] = ((const float4*)(Wl + (size_t)(kt + k) * OUT))[o4];
            ((float4*)Wsr[k])[o4] = ((const float4*)(Wr + (size_t)(kt + k) * OUT))[o4];
        }
        for (int idx = tid; idx < NPB * (KT / 4); idx += 256) {
            const int ni = idx / (KT / 4), f4 = idx % (KT / 4);
            const int gn = nb + ni;
            float4 xv = make_float4(0.f, 0.f, 0.f, 0.f);
            if (gn < NN)
                xv = ((const float4*)(X + (size_t)gn * IN + kt))[f4];
            Xs[f4 * 4 + 0][ni] = xv.x;
            Xs[f4 * 4 + 1][ni] = xv.y;
            Xs[f4 * 4 + 2][ni] = xv.z;
            Xs[f4 * 4 + 3][ni] = xv.w;
        }
        __syncthreads();
#pragma unroll
        for (int k = 0; k < KT; k++) {
            float xv[4];
#pragma unroll
            for (int i = 0; i < 4; i++) xv[i] = Xs[k][ng * 4 + i];
            const float4 wl0 = ((const float4*)&Wsl[k][og * 8])[0];
            const float4 wl1 = ((const float4*)&Wsl[k][og * 8])[1];
            const float4 wr0 = ((const float4*)&Wsr[k][og * 8])[0];
            const float4 wr1 = ((const float4*)&Wsr[k][og * 8])[1];
#pragma unroll
            for (int i = 0; i < 4; i++) {
                accl[i][0] += xv[i] * wl0.x; accl[i][1] += xv[i] * wl0.y;
                accl[i][2] += xv[i] * wl0.z; accl[i][3] += xv[i] * wl0.w;
                accl[i][4] += xv[i] * wl1.x; accl[i][5] += xv[i] * wl1.y;
                accl[i][6] += xv[i] * wl1.z; accl[i][7] += xv[i] * wl1.w;
                accr[i][0] += xv[i] * wr0.x; accr[i][1] += xv[i] * wr0.y;
                accr[i][2] += xv[i] * wr0.z; accr[i][3] += xv[i] * wr0.w;
                accr[i][4] += xv[i] * wr1.x; accr[i][5] += xv[i] * wr1.y;
                accr[i][6] += xv[i] * wr1.z; accr[i][7] += xv[i] * wr1.w;
            }
        }
    }

    const float4 bl0 = ((const float4*)(Bl + og * 8))[0];
    const float4 bl1 = ((const float4*)(Bl + og * 8))[1];
    const float4 br0 = ((const float4*)(Br + og * 8))[0];
    const float4 br1 = ((const float4*)(Br + og * 8))[1];
#pragma unroll
    for (int i = 0; i < 4; i++) {
        const int node = nb + ng * 4 + i;
        if (node >= NN) continue;
        float4 o;
        o = make_float4(accl[i][0]+bl0.x, accl[i][1]+bl0.y, accl[i][2]+bl0.z, accl[i][3]+bl0.w);
        ((float4*)(Yl + (size_t)node * OUT + og * 8))[0] = o;
        o = make_float4(accl[i][4]+bl1.x, accl[i][5]+bl1.y, accl[i][6]+bl1.z, accl[i][7]+bl1.w);
        ((float4*)(Yl + (size_t)node * OUT + og * 8))[1] = o;
        o = make_float4(accr[i][0]+br0.x, accr[i][1]+br0.y, accr[i][2]+br0.z, accr[i][3]+br0.w);
        ((float4*)(Yr + (size_t)node * OUT + og * 8))[0] = o;
        o = make_float4(accr[i][4]+br1.x, accr[i][5]+br1.y, accr[i][6]+br1.z, accr[i][7]+br1.w);
        ((float4*)(Yr + (size_t)node * OUT + og * 8))[1] = o;
    }
}

// ---------------- fused GATv2 edge pass (CT=128, H=2), warp/dst -------------
// ILP4 online softmax with 1-deep software pipeline on the quad gathers.
__global__ void gat_fused128_kernel(const float* __restrict__ att,
                                    const float* __restrict__ B,
                                    float* __restrict__ out) {
    const int node = (blockIdx.x * blockDim.x + threadIdx.x) >> 5;
    if (node >= NN) return;
    const int lane = threadIdx.x & 31;

    const float4 xrv  = *(const float4*)(g_xr + (size_t)node * 128 + lane * 4);
    const float4 attv = *(const float4*)(att + lane * 4);

    int p  = g_rowptr[node];
    const int pe = g_rowptr[node + 1];

    float  m[4] = {-INFINITY, -INFINITY, -INFINITY, -INFINITY};
    float  dd[4] = {0.f, 0.f, 0.f, 0.f};
    float4 A[4];
#pragma unroll
    for (int j = 0; j < 4; j++) A[j] = make_float4(0.f, 0.f, 0.f, 0.f);

    float4 a[4];
    bool have = (p + 3 < pe);
    if (have) {
#pragma unroll
        for (int j = 0; j < 4; j++) {
            const int s = __ldg(g_csrc + p + j);
            a[j] = __ldg((const float4*)(g_xl + (size_t)s * 128 + lane * 4));
        }
    }
    while (have) {
        const int pn = p + 4;
        const bool have_n = (pn + 3 < pe);
        float4 an[4];
        if (have_n) {        // issue next quad's gathers before current compute
#pragma unroll
            for (int j = 0; j < 4; j++) {
                const int s = __ldg(g_csrc + pn + j);
                an[j] = __ldg((const float4*)(g_xl + (size_t)s * 128 + lane * 4));
            }
        }

        float pp[4];
#pragma unroll
        for (int j = 0; j < 4; j++) {
            float t, sc = 0.f;
            t = a[j].x + xrv.x; t = t > 0.f ? t : 0.2f * t; sc += t * attv.x;
            t = a[j].y + xrv.y; t = t > 0.f ? t : 0.2f * t; sc += t * attv.y;
            t = a[j].z + xrv.z; t = t > 0.f ? t : 0.2f * t; sc += t * attv.z;
            t = a[j].w + xrv.w; t = t > 0.f ? t : 0.2f * t; sc += t * attv.w;
            pp[j] = sc;
        }
#pragma unroll
        for (int off = 1; off <= 8; off <<= 1)
#pragma unroll
            for (int j = 0; j < 4; j++)
                pp[j] += __shfl_xor_sync(0xffffffffu, pp[j], off);
#pragma unroll
        for (int j = 0; j < 4; j++) {
            const float nm = fmaxf(m[j], pp[j]);
            const float sc = __expf(m[j] - nm);
            const float w  = __expf(pp[j] - nm);
            dd[j] = dd[j] * sc + w;
            A[j].x = A[j].x * sc + w * a[j].x;
            A[j].y = A[j].y * sc + w * a[j].y;
            A[j].z = A[j].z * sc + w * a[j].z;
            A[j].w = A[j].w * sc + w * a[j].w;
            m[j] = nm;
        }
        p = pn;
        if (have_n) {
#pragma unroll
            for (int j = 0; j < 4; j++) a[j] = an[j];
        }
        have = have_n;
    }
    for (; p < pe; ++p) {   // tail -> state 0
        const int s0 = __ldg(g_csrc + p);
        const float4 a0 = __ldg((const float4*)(g_xl + (size_t)s0 * 128 + lane * 4));
        float t, p0 = 0.f;
        t = a0.x + xrv.x; t = t > 0.f ? t : 0.2f * t; p0 += t * attv.x;
        t = a0.y + xrv.y; t = t > 0.f ? t : 0.2f * t; p0 += t * attv.y;
        t = a0.z + xrv.z; t = t > 0.f ? t : 0.2f * t; p0 += t * attv.z;
        t = a0.w + xrv.w; t = t > 0.f ? t : 0.2f * t; p0 += t * attv.w;
#pragma unroll
        for (int off = 1; off <= 8; off <<= 1)
            p0 += __shfl_xor_sync(0xffffffffu, p0, off);
        const float nm = fmaxf(m[0], p0);
        const float sc = __expf(m[0] - nm);
        const float w  = __expf(p0 - nm);
        dd[0] = dd[0] * sc + w;
        A[0].x = A[0].x * sc + w * a0.x;
        A[0].y = A[0].y * sc + w * a0.y;
        A[0].z = A[0].z * sc + w * a0.z;
        A[0].w = A[0].w * sc + w * a0.w;
        m[0] = nm;
    }
    // merge 4 states (m[0] always finite: deg >= 1)
    float M = fmaxf(fmaxf(m[0], m[1]), fmaxf(m[2], m[3]));
    float d = 0.f;
    float4 acc = make_float4(0.f, 0.f, 0.f, 0.f);
#pragma unroll
    for (int j = 0; j < 4; j++) {
        const float sj = (m[j] == -INFINITY) ? 0.f : __expf(m[j] - M);
        d += dd[j] * sj;
        acc.x += A[j].x * sj; acc.y += A[j].y * sj;
        acc.z += A[j].z * sj; acc.w += A[j].w * sj;
    }

    const float inv = 1.f / (d + 1e-16f);
    const float4 bv = *(const float4*)(B + lane * 4);
    float4 o;
    o.x = acc.x * inv + bv.x; o.x = o.x > 0.f ? o.x : expm1f(o.x);
    o.y = acc.y * inv + bv.y; o.y = o.y > 0.f ? o.y : expm1f(o.y);
    o.z = acc.z * inv + bv.z; o.z = o.z > 0.f ? o.z : expm1f(o.z);
    o.w = acc.w * inv + bv.w; o.w = o.w > 0.f ? o.w : expm1f(o.w);
    *(float4*)(out + (size_t)node * 128 + lane * 4) = o;
}

// ---------------- fused GATv2 edge pass (CT=32, H=1), warp/dst, ILP4 --------
__global__ void gat_fused32_kernel(const float* __restrict__ att,
                                   const float* __restrict__ B,
                                   float* __restrict__ out) {
    const int node = (blockIdx.x * blockDim.x + threadIdx.x) >> 5;
    if (node >= NN) return;
    const int lane = threadIdx.x & 31;

    const float xrv  = g_xr[(size_t)node * 32 + lane];
    const float attv = att[lane];

    int p  = g_rowptr[node];
    const int pe = g_rowptr[node + 1];

    float m[4] = {-INFINITY, -INFINITY, -INFINITY, -INFINITY};
    float dd[4] = {0.f, 0.f, 0.f, 0.f};
    float A[4] = {0.f, 0.f, 0.f, 0.f};

    for (; p + 3 < pe; p += 4) {
        float a[4], pp[4];
#pragma unroll
        for (int j = 0; j < 4; j++) {
            const int s = __ldg(g_csrc + p + j);
            a[j] = __ldg(g_xl + (size_t)s * 32 + lane);
            float t = a[j] + xrv; t = t > 0.f ? t : 0.2f * t;
            pp[j] = t * attv;
        }
#pragma unroll
        for (int off = 1; off <= 16; off <<= 1)
#pragma unroll
            for (int j = 0; j < 4; j++)
                pp[j] += __shfl_xor_sync(0xffffffffu, pp[j], off);
#pragma unroll
        for (int j = 0; j < 4; j++) {
            const float nm = fmaxf(m[j], pp[j]);
            const float sc = __expf(m[j] - nm);
            const float w  = __expf(pp[j] - nm);
            dd[j] = dd[j] * sc + w; A[j] = A[j] * sc + w * a[j]; m[j] = nm;
        }
    }
    for (; p < pe; ++p) {
        const int s = __ldg(g_csrc + p);
        const float a0 = __ldg(g_xl + (size_t)s * 32 + lane);
        float t = a0 + xrv; t = t > 0.f ? t : 0.2f * t;
        float p0 = t * attv;
#pragma unroll
        for (int off = 1; off <= 16; off <<= 1)
            p0 += __shfl_xor_sync(0xffffffffu, p0, off);
        const float nm = fmaxf(m[0], p0);
        const float sc = __expf(m[0] - nm);
        const float w  = __expf(p0 - nm);
        dd[0] = dd[0] * sc + w; A[0] = A[0] * sc + w * a0; m[0] = nm;
    }
    float M = fmaxf(fmaxf(m[0], m[1]), fmaxf(m[2], m[3]));
    float d = 0.f, acc = 0.f;
#pragma unroll
    for (int j = 0; j < 4; j++) {
        const float sj = (m[j] == -INFINITY) ? 0.f : __expf(m[j] - M);
        d += dd[j] * sj; acc += A[j] * sj;
    }

    float o = acc / (d + 1e-16f) + B[lane];
    o = o > 0.f ? o : expm1f(o);
    out[(size_t)node * 32 + lane] = o;
}

// ---------------- pooling ----------------------------------------------------
__global__ void pool_init_kernel() {
    int i = blockIdx.x * blockDim.x + threadIdx.x;
    if (i < NG * 32) { g_psum[i] = 0.f; g_pmax[i] = -INFINITY; }
    if (i < NG) g_cntf[i] = 0.f;
}

__global__ __launch_bounds__(256)
void pool_accum_kernel(const float* __restrict__ h,
                       const int* __restrict__ batch) {
    __shared__ float ssum[NG * 32];
    __shared__ float smax[NG * 32];
    __shared__ int   scnt[NG];
    const int tid = threadIdx.x;
    for (int i = tid; i < NG * 32; i += 256) { ssum[i] = 0.f; smax[i] = -INFINITY; }
    if (tid < NG) scnt[tid] = 0;
    __syncthreads();

    const int warp = tid >> 5, lane = tid & 31;
    const int nbase = blockIdx.x * 256 + warp * 32;
#pragma unroll 4
    for (int i = 0; i < 32; i++) {
        const int node = nbase + i;
        if (node >= NN) break;
        const int g = batch[node];
        const float v = h[(size_t)node * 32 + lane];
        atomicAdd(&ssum[g * 32 + lane], v);
        atomicMaxF(&smax[g * 32 + lane], v);
        if (lane == 0) atomicAdd(&scnt[g], 1);
    }
    __syncthreads();

    for (int i = tid; i < NG * 32; i += 256) {
        if (ssum[i] != 0.f) atomicAdd(&g_psum[i], ssum[i]);
        if (smax[i] != -INFINITY) atomicMaxF(&g_pmax[i], smax[i]);
    }
    if (tid < NG && scnt[tid] > 0) atomicAdd(&g_cntf[tid], (float)scnt[tid]);
}

__global__ void pool_final_kernel(float* __restrict__ out) {
    const int i = blockIdx.x * blockDim.x + threadIdx.x;
    if (i >= NG * 64) return;
    const int g = i / 64, c = i % 64;
    out[i] = (c < 32) ? g_psum[g * 32 + c] / g_cntf[g]
                      : g_pmax[g * 32 + (c - 32)];
}

// ---------------- launch ------------------------------------------------------
static inline int gridFor(long long n) { return (int)((n + TB - 1) / TB); }

extern "C" void kernel_launch(void* const* d_in, const int* in_sizes, int n_in,
                              void* d_out, int out_size) {
    const float* x     = (const float*)d_in[0];
    const int*   ei    = (const int*)d_in[1];
    const int*   batch = (const int*)d_in[2];
    const float *Wl1=(const float*)d_in[3],  *bl1=(const float*)d_in[4];
    const float *Wr1=(const float*)d_in[5],  *br1=(const float*)d_in[6];
    const float *att1=(const float*)d_in[7], *b1=(const float*)d_in[8];
    const float *Wl2=(const float*)d_in[9],  *bl2=(const float*)d_in[10];
    const float *Wr2=(const float*)d_in[11], *br2=(const float*)d_in[12];
    const float *att2=(const float*)d_in[13],*b2=(const float*)d_in[14];
    const float *Wl3=(const float*)d_in[15], *bl3=(const float*)d_in[16];
    const float *Wr3=(const float*)d_in[17], *br3=(const float*)d_in[18];
    const float *att3=(const float*)d_in[19],*b3=(const float*)d_in[20];

    float *p_xl, *p_xr, *p_h;
    cudaGetSymbolAddress((void**)&p_xl, g_xl);
    cudaGetSymbolAddress((void**)&p_xr, g_xr);
    cudaGetSymbolAddress((void**)&p_h,  g_h);

    const int gNodeWarp = gridFor((long long)NN * 32);
    const int gLin128   = (NN + 63) / 64;
    const int gLin32    = (NN + 255) / 256;
    const int gPool     = (NN + 255) / 256;

    // ---- CSR (dst-indexed) build, reused by all 3 layers
    deg_init_kernel<<<gridFor(NN), TB>>>();
    deg_count_kernel<<<gridFor(NE), TB>>>(ei);
    scan_kernel<<<1, 1024>>>();
    fill_kernel<<<gridFor(ET), TB>>>(ei);

    // ---- layer 1: 8 -> 128 (H=2, C=64)
    linear_dual_kernel<8, 128><<<gLin128, 256>>>(x, Wl1, bl1, Wr1, br1, p_xl, p_xr);
    gat_fused128_kernel<<<gNodeWarp, TB>>>(att1, b1, p_h);

    // ---- layer 2: 128 -> 128 (H=2, C=64)
    linear_dual_kernel<128, 128><<<gLin128, 256>>>(p_h, Wl2, bl2, Wr2, br2, p_xl, p_xr);
    gat_fused128_kernel<<<gNodeWarp, TB>>>(att2, b2, p_h);

    // ---- layer 3: 128 -> 32 (H=1, C=32)
    linear_dual_kernel<128, 32><<<gLin32, 256>>>(p_h, Wl3, bl3, Wr3, br3, p_xl, p_xr);
    gat_fused32_kernel<<<gNodeWarp, TB>>>(att3, b3, p_h);

    // ---- pooling
    pool_init_kernel<<<gridFor(NG * 32), TB>>>();
    pool_accum_kernel<<<gPool, 256>>>(p_h, batch);
    pool_final_kernel<<<gridFor(NG * 64), TB>>>((float*)d_out);
}

// round 9
// speedup vs baseline: 1.6217x; 1.2258x over previous
#include <cuda_runtime.h>
#include <math.h>

// GATv2 x3 + pooling: CSR + offset-softmax (shift-invariant, no online chain)
// fused edge pass with ILP4, dual (Wl+Wr) register-tiled linears, SMEM pooling.
namespace {
constexpr int NN = 50000;
constexpr int NE = 800000;
constexpr int ET = NE + NN;
constexpr int NG = 16;
constexpr int TB = 256;
}

// ---------------- scratch ---------------------------------------------------
__device__ __align__(16) float g_xl[(size_t)NN * 128];
__device__ __align__(16) float g_xr[(size_t)NN * 128];
__device__ __align__(16) float g_h[(size_t)NN * 128];
__device__ int g_deg[NN];
__device__ int g_rowptr[NN + 1];
__device__ int g_cur[NN];
__device__ int g_csrc[ET];
__device__ float g_psum[NG * 32];
__device__ float g_pmax[NG * 32];
__device__ float g_cntf[NG];

__device__ __forceinline__ void atomicMaxF(float* a, float v) {
    if (v >= 0.f) atomicMax((int*)a, __float_as_int(v));
    else          atomicMin((unsigned int*)a, __float_as_uint(v));
}

// ---------------- CSR build -------------------------------------------------
__global__ void deg_count_kernel(const int* __restrict__ ei) {
    int e = blockIdx.x * blockDim.x + threadIdx.x;
    if (e < NN) {}  // nothing
    if (e < NE) atomicAdd(&g_deg[ei[NE + e]], 1);
}
__global__ void deg_init_kernel() {
    int i = blockIdx.x * blockDim.x + threadIdx.x;
    if (i < NN) g_deg[i] = 1;            // self loop
}
__global__ void scan_kernel() {
    __shared__ int part[1024];
    const int tid = threadIdx.x;
    const int chunk = (NN + 1023) / 1024;
    const int beg = tid * chunk;
    const int end = min(beg + chunk, NN);
    int s = 0;
    for (int i = beg; i < end; i++) s += g_deg[i];
    part[tid] = s;
    __syncthreads();
    if (tid == 0) {
        int run = 0;
        for (int i = 0; i < 1024; i++) { int t = part[i]; part[i] = run; run += t; }
    }
    __syncthreads();
    int run = part[tid];
    for (int i = beg; i < end; i++) {
        g_rowptr[i] = run;
        g_cur[i] = run;
        run += g_deg[i];
    }
    if (tid == 0) g_rowptr[NN] = ET;
}
__global__ void fill_kernel(const int* __restrict__ ei) {
    int e = blockIdx.x * blockDim.x + threadIdx.x;
    if (e >= ET) return;
    int src, dst;
    if (e < NE) { src = ei[e]; dst = ei[NE + e]; }
    else        { src = e - NE; dst = src; }
    int pos = atomicAdd(&g_cur[dst], 1);
    g_csrc[pos] = src;
}

// ---------------- dual linear: Yl = X@Wl+Bl, Yr = X@Wr+Br -------------------
template<int IN, int OUT>
__global__ __launch_bounds__(256)
void linear_dual_kernel(const float* __restrict__ X,
                        const float* __restrict__ Wl, const float* __restrict__ Bl,
                        const float* __restrict__ Wr, const float* __restrict__ Br,
                        float* __restrict__ Yl, float* __restrict__ Yr) {
    constexpr int TO  = OUT / 8;
    constexpr int NGR = 256 / TO;
    constexpr int NPB = NGR * 4;
    constexpr int KT  = (IN < 32) ? IN : 32;

    __shared__ float Xs[KT][NPB + 4];
    __shared__ float Wsl[KT][OUT];
    __shared__ float Wsr[KT][OUT];

    const int tid = threadIdx.x;
    const int og  = tid % TO;
    const int ng  = tid / TO;
    const int nb  = blockIdx.x * NPB;

    float accl[4][8], accr[4][8];
#pragma unroll
    for (int i = 0; i < 4; i++)
#pragma unroll
        for (int j = 0; j < 8; j++) { accl[i][j] = 0.f; accr[i][j] = 0.f; }

    for (int kt = 0; kt < IN; kt += KT) {
        __syncthreads();
        for (int idx = tid; idx < KT * OUT / 4; idx += 256) {
            const int k = idx / (OUT / 4), o4 = idx % (OUT / 4);
            ((float4*)Wsl[k])[o4] = ((const float4*)(Wl + (size_t)(kt + k) * OUT))[o4];
            ((float4*)Wsr[k])[o4] = ((const float4*)(Wr + (size_t)(kt + k) * OUT))[o4];
        }
        for (int idx = tid; idx < NPB * (KT / 4); idx += 256) {
            const int ni = idx / (KT / 4), f4 = idx % (KT / 4);
            const int gn = nb + ni;
            float4 xv = make_float4(0.f, 0.f, 0.f, 0.f);
            if (gn < NN)
                xv = ((const float4*)(X + (size_t)gn * IN + kt))[f4];
            Xs[f4 * 4 + 0][ni] = xv.x;
            Xs[f4 * 4 + 1][ni] = xv.y;
            Xs[f4 * 4 + 2][ni] = xv.z;
            Xs[f4 * 4 + 3][ni] = xv.w;
        }
        __syncthreads();
#pragma unroll
        for (int k = 0; k < KT; k++) {
            float xv[4];
#pragma unroll
            for (int i = 0; i < 4; i++) xv[i] = Xs[k][ng * 4 + i];
            const float4 wl0 = ((const float4*)&Wsl[k][og * 8])[0];
            const float4 wl1 = ((const float4*)&Wsl[k][og * 8])[1];
            const float4 wr0 = ((const float4*)&Wsr[k][og * 8])[0];
            const float4 wr1 = ((const float4*)&Wsr[k][og * 8])[1];
#pragma unroll
            for (int i = 0; i < 4; i++) {
                accl[i][0] += xv[i] * wl0.x; accl[i][1] += xv[i] * wl0.y;
                accl[i][2] += xv[i] * wl0.z; accl[i][3] += xv[i] * wl0.w;
                accl[i][4] += xv[i] * wl1.x; accl[i][5] += xv[i] * wl1.y;
                accl[i][6] += xv[i] * wl1.z; accl[i][7] += xv[i] * wl1.w;
                accr[i][0] += xv[i] * wr0.x; accr[i][1] += xv[i] * wr0.y;
                accr[i][2] += xv[i] * wr0.z; accr[i][3] += xv[i] * wr0.w;
                accr[i][4] += xv[i] * wr1.x; accr[i][5] += xv[i] * wr1.y;
                accr[i][6] += xv[i] * wr1.z; accr[i][7] += xv[i] * wr1.w;
            }
        }
    }

    const float4 bl0 = ((const float4*)(Bl + og * 8))[0];
    const float4 bl1 = ((const float4*)(Bl + og * 8))[1];
    const float4 br0 = ((const float4*)(Br + og * 8))[0];
    const float4 br1 = ((const float4*)(Br + og * 8))[1];
#pragma unroll
    for (int i = 0; i < 4; i++) {
        const int node = nb + ng * 4 + i;
        if (node >= NN) continue;
        float4 o;
        o = make_float4(accl[i][0]+bl0.x, accl[i][1]+bl0.y, accl[i][2]+bl0.z, accl[i][3]+bl0.w);
        ((float4*)(Yl + (size_t)node * OUT + og * 8))[0] = o;
        o = make_float4(accl[i][4]+bl1.x, accl[i][5]+bl1.y, accl[i][6]+bl1.z, accl[i][7]+bl1.w);
        ((float4*)(Yl + (size_t)node * OUT + og * 8))[1] = o;
        o = make_float4(accr[i][0]+br0.x, accr[i][1]+br0.y, accr[i][2]+br0.z, accr[i][3]+br0.w);
        ((float4*)(Yr + (size_t)node * OUT + og * 8))[0] = o;
        o = make_float4(accr[i][4]+br1.x, accr[i][5]+br1.y, accr[i][6]+br1.z, accr[i][7]+br1.w);
        ((float4*)(Yr + (size_t)node * OUT + og * 8))[1] = o;
    }
}

// ---------------- fused GATv2 edge pass (CT=128, H=2), warp/dst, ILP4 -------
// offset softmax: w = exp(s - s_self); shift-invariance makes this exact.
__global__ void gat_fused128_kernel(const float* __restrict__ att,
                                    const float* __restrict__ B,
                                    float* __restrict__ out) {
    const int node = (blockIdx.x * blockDim.x + threadIdx.x) >> 5;
    if (node >= NN) return;
    const int lane = threadIdx.x & 31;

    const float4 xrv  = *(const float4*)(g_xr + (size_t)node * 128 + lane * 4);
    const float4 attv = *(const float4*)(att + lane * 4);

    // per-node offset: the self-loop score (local data only)
    float s_self;
    {
        const float4 xlv = *(const float4*)(g_xl + (size_t)node * 128 + lane * 4);
        float t, sc = 0.f;
        t = xlv.x + xrv.x; t = t > 0.f ? t : 0.2f * t; sc += t * attv.x;
        t = xlv.y + xrv.y; t = t > 0.f ? t : 0.2f * t; sc += t * attv.y;
        t = xlv.z + xrv.z; t = t > 0.f ? t : 0.2f * t; sc += t * attv.z;
        t = xlv.w + xrv.w; t = t > 0.f ? t : 0.2f * t; sc += t * attv.w;
#pragma unroll
        for (int off = 1; off <= 8; off <<= 1)
            sc += __shfl_xor_sync(0xffffffffu, sc, off);
        s_self = sc;
    }

    int p  = g_rowptr[node];
    const int pe = g_rowptr[node + 1];

    float  dd[4] = {0.f, 0.f, 0.f, 0.f};
    float4 A[4];
#pragma unroll
    for (int j = 0; j < 4; j++) A[j] = make_float4(0.f, 0.f, 0.f, 0.f);

    for (; p + 3 < pe; p += 4) {
        int s[4];
#pragma unroll
        for (int j = 0; j < 4; j++) s[j] = g_csrc[p + j];
        float4 a[4];
#pragma unroll
        for (int j = 0; j < 4; j++)
            a[j] = *(const float4*)(g_xl + (size_t)s[j] * 128 + lane * 4);

        float pp[4];
#pragma unroll
        for (int j = 0; j < 4; j++) {
            float t, sc = 0.f;
            t = a[j].x + xrv.x; t = t > 0.f ? t : 0.2f * t; sc += t * attv.x;
            t = a[j].y + xrv.y; t = t > 0.f ? t : 0.2f * t; sc += t * attv.y;
            t = a[j].z + xrv.z; t = t > 0.f ? t : 0.2f * t; sc += t * attv.z;
            t = a[j].w + xrv.w; t = t > 0.f ? t : 0.2f * t; sc += t * attv.w;
            pp[j] = sc;
        }
#pragma unroll
        for (int off = 1; off <= 8; off <<= 1)
#pragma unroll
            for (int j = 0; j < 4; j++)
                pp[j] += __shfl_xor_sync(0xffffffffu, pp[j], off);
#pragma unroll
        for (int j = 0; j < 4; j++) {
            const float w = __expf(pp[j] - s_self);
            dd[j] += w;
            A[j].x += w * a[j].x;
            A[j].y += w * a[j].y;
            A[j].z += w * a[j].z;
            A[j].w += w * a[j].w;
        }
    }
    for (; p < pe; ++p) {
        const int s0 = g_csrc[p];
        const float4 a0 = *(const float4*)(g_xl + (size_t)s0 * 128 + lane * 4);
        float t, p0 = 0.f;
        t = a0.x + xrv.x; t = t > 0.f ? t : 0.2f * t; p0 += t * attv.x;
        t = a0.y + xrv.y; t = t > 0.f ? t : 0.2f * t; p0 += t * attv.y;
        t = a0.z + xrv.z; t = t > 0.f ? t : 0.2f * t; p0 += t * attv.z;
        t = a0.w + xrv.w; t = t > 0.f ? t : 0.2f * t; p0 += t * attv.w;
#pragma unroll
        for (int off = 1; off <= 8; off <<= 1)
            p0 += __shfl_xor_sync(0xffffffffu, p0, off);
        const float w = __expf(p0 - s_self);
        dd[0] += w;
        A[0].x += w * a0.x;
        A[0].y += w * a0.y;
        A[0].z += w * a0.z;
        A[0].w += w * a0.w;
    }

    const float d = dd[0] + dd[1] + dd[2] + dd[3];
    float4 acc;
    acc.x = A[0].x + A[1].x + A[2].x + A[3].x;
    acc.y = A[0].y + A[1].y + A[2].y + A[3].y;
    acc.z = A[0].z + A[1].z + A[2].z + A[3].z;
    acc.w = A[0].w + A[1].w + A[2].w + A[3].w;

    const float inv = 1.f / d;
    const float4 bv = *(const float4*)(B + lane * 4);
    float4 o;
    o.x = acc.x * inv + bv.x; o.x = o.x > 0.f ? o.x : expm1f(o.x);
    o.y = acc.y * inv + bv.y; o.y = o.y > 0.f ? o.y : expm1f(o.y);
    o.z = acc.z * inv + bv.z; o.z = o.z > 0.f ? o.z : expm1f(o.z);
    o.w = acc.w * inv + bv.w; o.w = o.w > 0.f ? o.w : expm1f(o.w);
    *(float4*)(out + (size_t)node * 128 + lane * 4) = o;
}

// ---------------- fused GATv2 edge pass (CT=32, H=1), warp/dst, ILP4 --------
__global__ void gat_fused32_kernel(const float* __restrict__ att,
                                   const float* __restrict__ B,
                                   float* __restrict__ out) {
    const int node = (blockIdx.x * blockDim.x + threadIdx.x) >> 5;
    if (node >= NN) return;
    const int lane = threadIdx.x & 31;

    const float xrv  = g_xr[(size_t)node * 32 + lane];
    const float attv = att[lane];

    float s_self;
    {
        const float xlv = g_xl[(size_t)node * 32 + lane];
        float t = xlv + xrv; t = t > 0.f ? t : 0.2f * t;
        float sc = t * attv;
#pragma unroll
        for (int off = 1; off <= 16; off <<= 1)
            sc += __shfl_xor_sync(0xffffffffu, sc, off);
        s_self = sc;
    }

    int p  = g_rowptr[node];
    const int pe = g_rowptr[node + 1];

    float dd[4] = {0.f, 0.f, 0.f, 0.f};
    float A[4] = {0.f, 0.f, 0.f, 0.f};

    for (; p + 3 < pe; p += 4) {
        float a[4], pp[4];
#pragma unroll
        for (int j = 0; j < 4; j++) {
            const int s = g_csrc[p + j];
            a[j] = g_xl[(size_t)s * 32 + lane];
            float t = a[j] + xrv; t = t > 0.f ? t : 0.2f * t;
            pp[j] = t * attv;
        }
#pragma unroll
        for (int off = 1; off <= 16; off <<= 1)
#pragma unroll
            for (int j = 0; j < 4; j++)
                pp[j] += __shfl_xor_sync(0xffffffffu, pp[j], off);
#pragma unroll
        for (int j = 0; j < 4; j++) {
            const float w = __expf(pp[j] - s_self);
            dd[j] += w; A[j] += w * a[j];
        }
    }
    for (; p < pe; ++p) {
        const int s = g_csrc[p];
        const float a0 = g_xl[(size_t)s * 32 + lane];
        float t = a0 + xrv; t = t > 0.f ? t : 0.2f * t;
        float p0 = t * attv;
#pragma unroll
        for (int off = 1; off <= 16; off <<= 1)
            p0 += __shfl_xor_sync(0xffffffffu, p0, off);
        const float w = __expf(p0 - s_self);
        dd[0] += w; A[0] += w * a0;
    }

    const float d = dd[0] + dd[1] + dd[2] + dd[3];
    const float acc = A[0] + A[1] + A[2] + A[3];

    float o = acc / d + B[lane];
    o = o > 0.f ? o : expm1f(o);
    out[(size_t)node * 32 + lane] = o;
}

// ---------------- pooling ----------------------------------------------------
__global__ void pool_init_kernel() {
    int i = blockIdx.x * blockDim.x + threadIdx.x;
    if (i < NG * 32) { g_psum[i] = 0.f; g_pmax[i] = -INFINITY; }
    if (i < NG) g_cntf[i] = 0.f;
}

__global__ __launch_bounds__(256)
void pool_accum_kernel(const float* __restrict__ h,
                       const int* __restrict__ batch) {
    __shared__ float ssum[NG * 32];
    __shared__ float smax[NG * 32];
    __shared__ int   scnt[NG];
    const int tid = threadIdx.x;
    for (int i = tid; i < NG * 32; i += 256) { ssum[i] = 0.f; smax[i] = -INFINITY; }
    if (tid < NG) scnt[tid] = 0;
    __syncthreads();

    const int warp = tid >> 5, lane = tid & 31;
    const int nbase = blockIdx.x * 256 + warp * 32;
#pragma unroll 4
    for (int i = 0; i < 32; i++) {
        const int node = nbase + i;
        if (node >= NN) break;
        const int g = batch[node];
        const float v = h[(size_t)node * 32 + lane];
        atomicAdd(&ssum[g * 32 + lane], v);
        atomicMaxF(&smax[g * 32 + lane], v);
        if (lane == 0) atomicAdd(&scnt[g], 1);
    }
    __syncthreads();

    for (int i = tid; i < NG * 32; i += 256) {
        if (ssum[i] != 0.f) atomicAdd(&g_psum[i], ssum[i]);
        if (smax[i] != -INFINITY) atomicMaxF(&g_pmax[i], smax[i]);
    }
    if (tid < NG && scnt[tid] > 0) atomicAdd(&g_cntf[tid], (float)scnt[tid]);
}

__global__ void pool_final_kernel(float* __restrict__ out) {
    const int i = blockIdx.x * blockDim.x + threadIdx.x;
    if (i >= NG * 64) return;
    const int g = i / 64, c = i % 64;
    out[i] = (c < 32) ? g_psum[g * 32 + c] / g_cntf[g]
                      : g_pmax[g * 32 + (c - 32)];
}

// ---------------- launch ------------------------------------------------------
static inline int gridFor(long long n) { return (int)((n + TB - 1) / TB); }

extern "C" void kernel_launch(void* const* d_in, const int* in_sizes, int n_in,
                              void* d_out, int out_size) {
    const float* x     = (const float*)d_in[0];
    const int*   ei    = (const int*)d_in[1];
    const int*   batch = (const int*)d_in[2];
    const float *Wl1=(const float*)d_in[3],  *bl1=(const float*)d_in[4];
    const float *Wr1=(const float*)d_in[5],  *br1=(const float*)d_in[6];
    const float *att1=(const float*)d_in[7], *b1=(const float*)d_in[8];
    const float *Wl2=(const float*)d_in[9],  *bl2=(const float*)d_in[10];
    const float *Wr2=(const float*)d_in[11], *br2=(const float*)d_in[12];
    const float *att2=(const float*)d_in[13],*b2=(const float*)d_in[14];
    const float *Wl3=(const float*)d_in[15], *bl3=(const float*)d_in[16];
    const float *Wr3=(const float*)d_in[17], *br3=(const float*)d_in[18];
    const float *att3=(const float*)d_in[19],*b3=(const float*)d_in[20];

    float *p_xl, *p_xr, *p_h;
    cudaGetSymbolAddress((void**)&p_xl, g_xl);
    cudaGetSymbolAddress((void**)&p_xr, g_xr);
    cudaGetSymbolAddress((void**)&p_h,  g_h);

    const int gNodeWarp = gridFor((long long)NN * 32);
    const int gLin128   = (NN + 63) / 64;
    const int gLin32    = (NN + 255) / 256;
    const int gPool     = (NN + 255) / 256;

    // ---- CSR (dst-indexed) build, reused by all 3 layers
    deg_init_kernel<<<gridFor(NN), TB>>>();
    deg_count_kernel<<<gridFor(NE), TB>>>(ei);
    scan_kernel<<<1, 1024>>>();
    fill_kernel<<<gridFor(ET), TB>>>(ei);

    // ---- layer 1: 8 -> 128 (H=2, C=64)
    linear_dual_kernel<8, 128><<<gLin128, 256>>>(x, Wl1, bl1, Wr1, br1, p_xl, p_xr);
    gat_fused128_kernel<<<gNodeWarp, TB>>>(att1, b1, p_h);

    // ---- layer 2: 128 -> 128 (H=2, C=64)
    linear_dual_kernel<128, 128><<<gLin128, 256>>>(p_h, Wl2, bl2, Wr2, br2, p_xl, p_xr);
    gat_fused128_kernel<<<gNodeWarp, TB>>>(att2, b2, p_h);

    // ---- layer 3: 128 -> 32 (H=1, C=32)
    linear_dual_kernel<128, 32><<<gLin32, 256>>>(p_h, Wl3, bl3, Wr3, br3, p_xl, p_xr);
    gat_fused32_kernel<<<gNodeWarp, TB>>>(att3, b3, p_h);

    // ---- pooling
    pool_init_kernel<<<gridFor(NG * 32), TB>>>();
    pool_accum_kernel<<<gPool, 256>>>(p_h, batch);
    pool_final_kernel<<<gridFor(NG * 64), TB>>>((float*)d_out);
}